// round 10
// baseline (speedup 1.0000x reference)
#include <cuda_runtime.h>
#include <math.h>
#include <float.h>

#define GRID  148
#define NT    256
#define CELLB 128      // blocks [0,CELLB) do LSTM cells; [CELLB,GRID) do MLP
#define NMLPB (GRID - CELLB)
#define Bn 64
#define Tn 2048
#define Ln 200
#define Hn 256
#define Vn 33

// ---------------- persistent device state ----------------
__device__ float gW0[1024 * 768];          // cell0 rows: [w_ih0_row(512) | w_hh0_row(256)]
__device__ float gW12[2 * 1024 * 512];     // cells 1,2 rows: [w_ih(256) | w_hh(256)]
__device__ float gBias[3 * 1024];          // b_ih + b_hh per layer
__device__ float g_h[2][3][Bn][Hn];        // double-buffered hidden states
__device__ float g_c[3][Bn][Hn];           // cell states (elementwise in-place safe)
__device__ float g_ctxU[Bn][Hn];           // UNnormalized context
__device__ float g_denom[Bn];              // softmax denominator
__device__ unsigned g_emax[Bn];            // ordered-uint encoded max energy
__device__ float g_e[Bn][Tn];              // energies
__device__ unsigned g_bar;                 // grid barrier counter

struct __align__(16) SM {
    union {
        struct { float xs[4][768]; float gsm[512]; } cell;   // 14.3 KB
        struct { float qs[256]; float wm[8]; } en;
        struct { float4 cs[8][64]; float rs[8]; } ctx;       // 8.2 KB
        struct { float zs[512]; float hs[512]; } mlp;        // 4 KB
    } u;
};

// ---------------- helpers ----------------
__device__ __forceinline__ float sigm(float x) { return 1.0f / (1.0f + __expf(-x)); }
__device__ __forceinline__ float tanhx(float x) {
    float e = __expf(-2.0f * fabsf(x));
    float r = (1.0f - e) / (1.0f + e);
    return x < 0.0f ? -r : r;
}
__device__ __forceinline__ unsigned ford(float f) {
    unsigned u = __float_as_uint(f);
    return (u & 0x80000000u) ? ~u : (u | 0x80000000u);
}
__device__ __forceinline__ float fdec(unsigned u) {
    return (u & 0x80000000u) ? __uint_as_float(u & 0x7fffffffu)
                             : __uint_as_float(~u);
}
__device__ __forceinline__ float dot4(float4 a, float4 b) {
    return fmaf(a.x, b.x, fmaf(a.y, b.y, fmaf(a.z, b.z, a.w * b.w)));
}

// grid-wide barrier: monotonic counter (reset by prep each launch)
__device__ __forceinline__ void gsync(unsigned &expect) {
    __syncthreads();
    if (threadIdx.x == 0) {
        expect += GRID;
        __threadfence();
        atomicAdd(&g_bar, 1u);
        while (*((volatile unsigned *)&g_bar) < expect) { }
        __threadfence();
    }
    __syncthreads();
}

// ---------------- prep: concat weights, zero state, reset barrier ----------------
__global__ void prep_kernel(const float *__restrict__ w_ih0, const float *__restrict__ w_hh0,
                            const float *__restrict__ b_ih0, const float *__restrict__ b_hh0,
                            const float *__restrict__ w_ih_r, const float *__restrict__ w_hh_r,
                            const float *__restrict__ b_ih_r, const float *__restrict__ b_hh_r)
{
    const int ns = gridDim.x * blockDim.x;
    const int t0 = blockIdx.x * blockDim.x + threadIdx.x;
    for (int i = t0; i < 1024 * 768; i += ns) {
        int r = i / 768, k = i - r * 768;
        gW0[i] = (k < 512) ? w_ih0[r * 512 + k] : w_hh0[r * 256 + (k - 512)];
    }
    for (int i = t0; i < 2 * 1024 * 512; i += ns) {
        int li = i >> 19;
        int rem = i & ((1 << 19) - 1);
        int r = rem >> 9, k = rem & 511;
        gW12[i] = (k < 256) ? w_ih_r[((size_t)li * 1024 + r) * 256 + k]
                            : w_hh_r[((size_t)li * 1024 + r) * 256 + (k - 256)];
    }
    for (int i = t0; i < 3 * 1024; i += ns) {
        int li = i >> 10, r = i & 1023;
        gBias[i] = (li == 0) ? (b_ih0[r] + b_hh0[r])
                             : (b_ih_r[(li - 1) * 1024 + r] + b_hh_r[(li - 1) * 1024 + r]);
    }
    for (int i = t0; i < 2 * 3 * Bn * Hn; i += ns) ((float *)g_h)[i] = 0.0f;
    for (int i = t0; i < 3 * Bn * Hn; i += ns) ((float *)g_c)[i] = 0.0f;
    for (int i = t0; i < Bn * Hn; i += ns) ((float *)g_ctxU)[i] = 0.0f;
    for (int i = t0; i < Bn; i += ns) { g_denom[i] = 1.0f; g_emax[i] = 0u; }
    if (t0 == 0) g_bar = 0u;
}

// ---------------- LSTM cell phase (blocks 0..127): tile 4b x 32j ----------------
__device__ void cell_phase(int L, int l, int cur, int prv,
                           const float *__restrict__ emb, const int *__restrict__ labels, SM *s)
{
    const int blk = blockIdx.x, tid = threadIdx.x;
    const int w = tid >> 5, lane = tid & 31;
    const int b0 = (blk >> 3) * 4;
    const int j0 = (blk & 7) * 32;
    const int Kc = (L == 0) ? 768 : 512;
    const float *W = (L == 0) ? gW0 : (gW12 + (size_t)(L - 1) * 1024 * 512);
    const float *bias = gBias + L * 1024;

    // stage xcat for 4 batches into smem
    if (L == 0) {
        for (int i = tid; i < 4 * 256; i += NT) {
            int bi = i >> 8, k = i & 255, b = b0 + bi;
            int lab = labels[l * Bn + b];
            float rd = 1.0f / g_denom[b];
            s->u.cell.xs[bi][k]       = emb[(size_t)lab * 256 + k];
            s->u.cell.xs[bi][256 + k] = g_ctxU[b][k] * rd;
            s->u.cell.xs[bi][512 + k] = g_h[prv][0][b][k];
        }
    } else {
        for (int i = tid; i < 4 * 256; i += NT) {
            int bi = i >> 8, k = i & 255, b = b0 + bi;
            s->u.cell.xs[bi][k]       = g_h[cur][L - 1][b][k];
            s->u.cell.xs[bi][256 + k] = g_h[prv][L][b][k];
        }
    }
    __syncthreads();

    const float4 *X0 = (const float4 *)s->u.cell.xs[0];
    const float4 *X1 = (const float4 *)s->u.cell.xs[1];
    const float4 *X2 = (const float4 *)s->u.cell.xs[2];
    const float4 *X3 = (const float4 *)s->u.cell.xs[3];
    const int C = Kc >> 7;   // 128-float chunks: 6 (cell0) or 4

    // 128 units = (gate g, jj) ; warp w handles units [16w, 16w+16)
    for (int i = 0; i < 16; i++) {
        int u = w * 16 + i;
        int g = u & 3, jj = u >> 2;
        int r = g * 256 + j0 + jj;
        const float4 *wr = (const float4 *)(W + (size_t)r * Kc);
        float a0 = 0.f, a1 = 0.f, a2 = 0.f, a3 = 0.f;
        for (int c = 0; c < C; c++) {
            float4 wv = wr[c * 32 + lane];
            a0 += dot4(wv, X0[c * 32 + lane]);
            a1 += dot4(wv, X1[c * 32 + lane]);
            a2 += dot4(wv, X2[c * 32 + lane]);
            a3 += dot4(wv, X3[c * 32 + lane]);
        }
        for (int off = 16; off; off >>= 1) {
            a0 += __shfl_xor_sync(0xffffffffu, a0, off);
            a1 += __shfl_xor_sync(0xffffffffu, a1, off);
            a2 += __shfl_xor_sync(0xffffffffu, a2, off);
            a3 += __shfl_xor_sync(0xffffffffu, a3, off);
        }
        if (lane == 0) {
            float bb = bias[r];
            s->u.cell.gsm[(jj * 4 + g) * 4 + 0] = a0 + bb;
            s->u.cell.gsm[(jj * 4 + g) * 4 + 1] = a1 + bb;
            s->u.cell.gsm[(jj * 4 + g) * 4 + 2] = a2 + bb;
            s->u.cell.gsm[(jj * 4 + g) * 4 + 3] = a3 + bb;
        }
    }
    __syncthreads();
    if (tid < 128) {
        int jj = tid >> 2, bi = tid & 3;
        int b = b0 + bi, j = j0 + jj;
        float gi = s->u.cell.gsm[(jj * 4 + 0) * 4 + bi];
        float gf = s->u.cell.gsm[(jj * 4 + 1) * 4 + bi];
        float gg = s->u.cell.gsm[(jj * 4 + 2) * 4 + bi];
        float go = s->u.cell.gsm[(jj * 4 + 3) * 4 + bi];
        float co = g_c[L][b][j];
        float cn = sigm(gf) * co + sigm(gi) * tanhx(gg);
        g_c[L][b][j] = cn;
        g_h[cur][L][b][j] = sigm(go) * tanhx(cn);
    }
}

// ---------------- MLP head for one batch ----------------
__device__ void mlp_b(int b, int hp, int ol,
                      const float *__restrict__ fc1w, const float *__restrict__ fc1b,
                      const float *__restrict__ fc2w, const float *__restrict__ fc2b,
                      float *__restrict__ out, SM *s)
{
    const int tid = threadIdx.x, w = tid >> 5, lane = tid & 31;
    __syncthreads();
    float rd = 1.0f / g_denom[b];
    s->u.mlp.zs[tid]       = g_h[hp][2][b][tid];
    s->u.mlp.zs[256 + tid] = g_ctxU[b][tid] * rd;
    __syncthreads();
    const float4 *z4 = (const float4 *)s->u.mlp.zs;
    float4 zr0 = z4[0 * 32 + lane], zr1 = z4[1 * 32 + lane];
    float4 zr2 = z4[2 * 32 + lane], zr3 = z4[3 * 32 + lane];
    for (int i = 0; i < 32; i++) {
        int r = w * 32 + i;
        const float4 *w0 = (const float4 *)(fc1w + (size_t)r * 512);
        const float4 *w1 = (const float4 *)(fc1w + (size_t)(r + 256) * 512);
        float a0 = dot4(w0[0 * 32 + lane], zr0) + dot4(w0[1 * 32 + lane], zr1)
                 + dot4(w0[2 * 32 + lane], zr2) + dot4(w0[3 * 32 + lane], zr3);
        float a1 = dot4(w1[0 * 32 + lane], zr0) + dot4(w1[1 * 32 + lane], zr1)
                 + dot4(w1[2 * 32 + lane], zr2) + dot4(w1[3 * 32 + lane], zr3);
        for (int off = 16; off; off >>= 1) {
            a0 += __shfl_xor_sync(0xffffffffu, a0, off);
            a1 += __shfl_xor_sync(0xffffffffu, a1, off);
        }
        if (lane == 0) {
            s->u.mlp.hs[r]       = fmaxf(a0 + fc1b[r], 0.0f);
            s->u.mlp.hs[r + 256] = fmaxf(a1 + fc1b[r + 256], 0.0f);
        }
    }
    __syncthreads();
    const float4 *h4 = (const float4 *)s->u.mlp.hs;
    for (int r = w; r < Vn; r += 8) {
        const float4 *wr = (const float4 *)(fc2w + (size_t)r * 512);
        float a = dot4(wr[0 * 32 + lane], h4[0 * 32 + lane])
                + dot4(wr[1 * 32 + lane], h4[1 * 32 + lane])
                + dot4(wr[2 * 32 + lane], h4[2 * 32 + lane])
                + dot4(wr[3 * 32 + lane], h4[3 * 32 + lane]);
        for (int off = 16; off; off >>= 1) a += __shfl_xor_sync(0xffffffffu, a, off);
        if (lane == 0) out[((size_t)b * Ln + ol) * Vn + r] = a + fc2b[r];
    }
}

// ---------------- energy: e[b,t] = key[b,t,:].q[b,:] for t < len[b] ----------------
__device__ void energy_phase(int cur, const float *__restrict__ key,
                             const int *__restrict__ lens, SM *s)
{
    const int blk = blockIdx.x, tid = threadIdx.x;
    const int w = tid >> 5, lane = tid & 31;
    for (int it = blk; it < Bn * 16; it += GRID) {
        int b = it >> 4;
        int t0 = (it & 15) << 7;
        int len = lens[b];
        if (t0 >= len) continue;
        int t1 = min(t0 + 128, len);
        __syncthreads();
        s->u.en.qs[tid] = g_h[cur][2][b][tid];
        __syncthreads();
        const float4 *q4 = (const float4 *)s->u.en.qs;
        float4 q0 = q4[lane], q1 = q4[lane + 32];
        float wmax = -FLT_MAX;
        for (int t = t0 + w; t < t1; t += 8) {
            const float4 *kr = (const float4 *)(key + ((size_t)b * Tn + t) * Hn);
            float4 k0 = kr[lane], k1 = kr[lane + 32];
            float sv = dot4(k0, q0) + dot4(k1, q1);
            sv += __shfl_xor_sync(0xffffffffu, sv, 16);
            sv += __shfl_xor_sync(0xffffffffu, sv, 8);
            sv += __shfl_xor_sync(0xffffffffu, sv, 4);
            sv += __shfl_xor_sync(0xffffffffu, sv, 2);
            sv += __shfl_xor_sync(0xffffffffu, sv, 1);
            if (lane == 0) g_e[b][t] = sv;
            wmax = fmaxf(wmax, sv);
        }
        if (lane == 0) s->u.en.wm[w] = wmax;
        __syncthreads();
        if (tid == 0) {
            float m = s->u.en.wm[0];
            for (int i = 1; i < 8; i++) m = fmaxf(m, s->u.en.wm[i]);
            if (m > -FLT_MAX) atomicMax(&g_emax[b], ford(m));
        }
    }
}

// ---------------- ctx: ctxU += exp(e - emax) * value ; denom += exp ----------------
__device__ void ctx_phase(const float *__restrict__ value,
                          const int *__restrict__ lens, SM *s)
{
    const int blk = blockIdx.x, tid = threadIdx.x;
    const int w = tid >> 5, lane = tid & 31;
    for (int it = blk; it < Bn * 16; it += GRID) {
        int b = it >> 4;
        int t0 = (it & 15) << 7;
        int len = lens[b];
        if (t0 >= len) continue;
        int t1 = min(t0 + 128, len);
        float em = fdec(g_emax[b]);
        float4 a0 = make_float4(0.f, 0.f, 0.f, 0.f);
        float4 a1 = make_float4(0.f, 0.f, 0.f, 0.f);
        float dp = 0.0f;
        for (int t = t0 + w; t < t1; t += 8) {
            float p = __expf(g_e[b][t] - em);
            const float4 *vr = (const float4 *)(value + ((size_t)b * Tn + t) * Hn);
            float4 v0 = vr[lane], v1 = vr[lane + 32];
            a0.x = fmaf(p, v0.x, a0.x); a0.y = fmaf(p, v0.y, a0.y);
            a0.z = fmaf(p, v0.z, a0.z); a0.w = fmaf(p, v0.w, a0.w);
            a1.x = fmaf(p, v1.x, a1.x); a1.y = fmaf(p, v1.y, a1.y);
            a1.z = fmaf(p, v1.z, a1.z); a1.w = fmaf(p, v1.w, a1.w);
            if (lane == 0) dp += p;
        }
        __syncthreads();
        s->u.ctx.cs[w][lane] = a0;
        s->u.ctx.cs[w][lane + 32] = a1;
        if (lane == 0) s->u.ctx.rs[w] = dp;
        __syncthreads();
        if (tid < 64) {
            float4 sum = s->u.ctx.cs[0][tid];
            for (int i = 1; i < 8; i++) {
                float4 v = s->u.ctx.cs[i][tid];
                sum.x += v.x; sum.y += v.y; sum.z += v.z; sum.w += v.w;
            }
            atomicAdd(&g_ctxU[b][4 * tid + 0], sum.x);
            atomicAdd(&g_ctxU[b][4 * tid + 1], sum.y);
            atomicAdd(&g_ctxU[b][4 * tid + 2], sum.z);
            atomicAdd(&g_ctxU[b][4 * tid + 3], sum.w);
        } else if (tid == 64) {
            float d = 0.0f;
            for (int i = 0; i < 8; i++) d += s->u.ctx.rs[i];
            atomicAdd(&g_denom[b], d);
        }
    }
}

// ---------------- main persistent kernel ----------------
__global__ __launch_bounds__(NT) void decoder_kernel(
    const float *__restrict__ key, const float *__restrict__ value,
    const int *__restrict__ labels, const int *__restrict__ lens,
    const float *__restrict__ emb,
    const float *__restrict__ fc1w, const float *__restrict__ fc1b,
    const float *__restrict__ fc2w, const float *__restrict__ fc2b,
    float *__restrict__ out)
{
    __shared__ SM s;
    const int blk = blockIdx.x, tid = threadIdx.x;
    unsigned expect = 0;

    for (int l = 0; l < Ln; l++) {
        const int cur = l & 1, prv = cur ^ 1;
        // ---- slot 1: cell0  |  MLP(l-1) part A (b in [0,22)) ----
        if (blk < CELLB) {
            cell_phase(0, l, cur, prv, emb, labels, &s);
        } else if (l > 0) {
            int m = blk - CELLB;
            for (int b = m; b < 22; b += NMLPB)
                mlp_b(b, prv, l - 1, fc1w, fc1b, fc2w, fc2b, out, &s);
        }
        gsync(expect);
        // ---- slot 2: cell1 + emax reset  |  MLP part B (b in [22,44)) ----
        if (blk < CELLB) {
            cell_phase(1, l, cur, prv, emb, labels, &s);
            if (blk == 0 && tid < Bn) g_emax[tid] = 0u;
        } else if (l > 0) {
            int m = blk - CELLB;
            for (int b = 22 + m; b < 44; b += NMLPB)
                mlp_b(b, prv, l - 1, fc1w, fc1b, fc2w, fc2b, out, &s);
        }
        gsync(expect);
        // ---- slot 3: cell2  |  MLP part C (b in [44,64)) ----
        if (blk < CELLB) {
            cell_phase(2, l, cur, prv, emb, labels, &s);
        } else if (l > 0) {
            int m = blk - CELLB;
            for (int b = 44 + m; b < 64; b += NMLPB)
                mlp_b(b, prv, l - 1, fc1w, fc1b, fc2w, fc2b, out, &s);
        }
        gsync(expect);
        // ---- slot 4: zero ctxU/denom + energy (+ per-b max) ----
        for (int i = blk * NT + tid; i < Bn * Hn; i += GRID * NT)
            ((float *)g_ctxU)[i] = 0.0f;
        if (blk == 0 && tid < Bn) g_denom[tid] = 0.0f;
        energy_phase(cur, key, lens, &s);
        gsync(expect);
        // ---- slot 5: ctx accumulation ----
        ctx_phase(value, lens, &s);
        gsync(expect);
    }
    // final MLP for l = Ln-1 (parity of 199 = 1)
    for (int b = blk; b < Bn; b += GRID)
        mlp_b(b, 1, Ln - 1, fc1w, fc1b, fc2w, fc2b, out, &s);
}

// ---------------- launch ----------------
extern "C" void kernel_launch(void *const *d_in, const int *in_sizes, int n_in,
                              void *d_out, int out_size)
{
    const float *key    = (const float *)d_in[0];
    const float *value  = (const float *)d_in[1];
    const int   *labels = (const int *)d_in[2];
    const int   *lens   = (const int *)d_in[3];
    const float *emb    = (const float *)d_in[4];
    const float *w_ih0  = (const float *)d_in[5];
    const float *w_hh0  = (const float *)d_in[6];
    const float *b_ih0  = (const float *)d_in[7];
    const float *b_hh0  = (const float *)d_in[8];
    const float *w_ih_r = (const float *)d_in[9];
    const float *w_hh_r = (const float *)d_in[10];
    const float *b_ih_r = (const float *)d_in[11];
    const float *b_hh_r = (const float *)d_in[12];
    const float *fc1w   = (const float *)d_in[13];
    const float *fc1b   = (const float *)d_in[14];
    const float *fc2w   = (const float *)d_in[15];
    const float *fc2b   = (const float *)d_in[16];
    float *out = (float *)d_out;

    prep_kernel<<<592, 256>>>(w_ih0, w_hh0, b_ih0, b_hh0,
                              w_ih_r, w_hh_r, b_ih_r, b_hh_r);
    decoder_kernel<<<GRID, NT>>>(key, value, labels, lens, emb,
                                 fc1w, fc1b, fc2w, fc2b, out);
}

// round 13
// speedup vs baseline: 1.4001x; 1.4001x over previous
#include <cuda_runtime.h>
#include <math.h>
#include <float.h>

#define GRID  148
#define NT    256
#define CELLB 128      // blocks [0,CELLB) do LSTM cells; [CELLB,GRID) do MLP
#define NMLPB (GRID - CELLB)
#define Bn 64
#define Tn 2048
#define Ln 200
#define Hn 256
#define Vn 33

// ---------------- persistent device state ----------------
__device__ float gW0[1024 * 768];          // cell0 rows: [w_ih0_row(512) | w_hh0_row(256)]
__device__ float gW12[2 * 1024 * 512];     // cells 1,2 rows: [w_ih(256) | w_hh(256)]
__device__ float gBias[3 * 1024];          // b_ih + b_hh per layer
__device__ float g_h[2][3][Bn][Hn];        // double-buffered hidden states
__device__ float g_c[3][Bn][Hn];           // cell states (elementwise in-place safe)
__device__ float g_ctxU[Bn][Hn];           // UNnormalized context
__device__ float g_denom[Bn];              // softmax denominator
__device__ unsigned g_emax[Bn];            // ordered-uint encoded max energy
__device__ float g_e[Bn][Tn];              // energies
__device__ unsigned g_bar;                 // grid barrier counter

struct __align__(16) SM {
    union {
        struct { float xs[4][768]; float gsm[512]; } cell;   // 14.3 KB
        struct { float qs[256]; float wm[8]; } en;
        struct { float4 cs[8][64]; float rs[8]; } ctx;       // 8.2 KB
        struct { float zs[512]; float hs[512]; } mlp;        // 4 KB
    } u;
};

// ---------------- helpers ----------------
__device__ __forceinline__ float sigm(float x) { return 1.0f / (1.0f + __expf(-x)); }
__device__ __forceinline__ float tanhx(float x) {
    float e = __expf(-2.0f * fabsf(x));
    float r = (1.0f - e) / (1.0f + e);
    return x < 0.0f ? -r : r;
}
__device__ __forceinline__ unsigned ford(float f) {
    unsigned u = __float_as_uint(f);
    return (u & 0x80000000u) ? ~u : (u | 0x80000000u);
}
__device__ __forceinline__ float fdec(unsigned u) {
    return (u & 0x80000000u) ? __uint_as_float(u & 0x7fffffffu)
                             : __uint_as_float(~u);
}
__device__ __forceinline__ float dot4(float4 a, float4 b) {
    return fmaf(a.x, b.x, fmaf(a.y, b.y, fmaf(a.z, b.z, a.w * b.w)));
}

// grid-wide barrier: monotonic counter (reset by prep each launch)
__device__ __forceinline__ void gsync(unsigned &expect) {
    __syncthreads();
    if (threadIdx.x == 0) {
        expect += GRID;
        __threadfence();
        atomicAdd(&g_bar, 1u);
        while (*((volatile unsigned *)&g_bar) < expect) { }
        __threadfence();
    }
    __syncthreads();
}

// ---------------- prep: concat weights, zero state, reset barrier ----------------
__global__ void prep_kernel(const float *__restrict__ w_ih0, const float *__restrict__ w_hh0,
                            const float *__restrict__ b_ih0, const float *__restrict__ b_hh0,
                            const float *__restrict__ w_ih_r, const float *__restrict__ w_hh_r,
                            const float *__restrict__ b_ih_r, const float *__restrict__ b_hh_r)
{
    const int ns = gridDim.x * blockDim.x;
    const int t0 = blockIdx.x * blockDim.x + threadIdx.x;
    for (int i = t0; i < 1024 * 768; i += ns) {
        int r = i / 768, k = i - r * 768;
        gW0[i] = (k < 512) ? w_ih0[r * 512 + k] : w_hh0[r * 256 + (k - 512)];
    }
    for (int i = t0; i < 2 * 1024 * 512; i += ns) {
        int li = i >> 19;
        int rem = i & ((1 << 19) - 1);
        int r = rem >> 9, k = rem & 511;
        gW12[i] = (k < 256) ? w_ih_r[((size_t)li * 1024 + r) * 256 + k]
                            : w_hh_r[((size_t)li * 1024 + r) * 256 + (k - 256)];
    }
    for (int i = t0; i < 3 * 1024; i += ns) {
        int li = i >> 10, r = i & 1023;
        gBias[i] = (li == 0) ? (b_ih0[r] + b_hh0[r])
                             : (b_ih_r[(li - 1) * 1024 + r] + b_hh_r[(li - 1) * 1024 + r]);
    }
    for (int i = t0; i < 2 * 3 * Bn * Hn; i += ns) ((float *)g_h)[i] = 0.0f;
    for (int i = t0; i < 3 * Bn * Hn; i += ns) ((float *)g_c)[i] = 0.0f;
    for (int i = t0; i < Bn * Hn; i += ns) ((float *)g_ctxU)[i] = 0.0f;
    for (int i = t0; i < Bn; i += ns) { g_denom[i] = 1.0f; g_emax[i] = 0u; }
    if (t0 == 0) g_bar = 0u;
}

// ---------------- LSTM cell phase (blocks 0..127): tile 4b x 32j ----------------
__device__ void cell_phase(int L, int l, int cur, int prv,
                           const float *__restrict__ emb, const int *__restrict__ labels, SM *s)
{
    const int blk = blockIdx.x, tid = threadIdx.x;
    const int w = tid >> 5, lane = tid & 31;
    const int b0 = (blk >> 3) * 4;
    const int j0 = (blk & 7) * 32;
    const int Kc = (L == 0) ? 768 : 512;
    const float *W = (L == 0) ? gW0 : (gW12 + (size_t)(L - 1) * 1024 * 512);
    const float *bias = gBias + L * 1024;

    // stage xcat for 4 batches into smem
    if (L == 0) {
        for (int i = tid; i < 4 * 256; i += NT) {
            int bi = i >> 8, k = i & 255, b = b0 + bi;
            int lab = labels[l * Bn + b];
            float rd = 1.0f / g_denom[b];
            s->u.cell.xs[bi][k]       = emb[(size_t)lab * 256 + k];
            s->u.cell.xs[bi][256 + k] = g_ctxU[b][k] * rd;
            s->u.cell.xs[bi][512 + k] = g_h[prv][0][b][k];
        }
    } else {
        for (int i = tid; i < 4 * 256; i += NT) {
            int bi = i >> 8, k = i & 255, b = b0 + bi;
            s->u.cell.xs[bi][k]       = g_h[cur][L - 1][b][k];
            s->u.cell.xs[bi][256 + k] = g_h[prv][L][b][k];
        }
    }
    __syncthreads();

    const float4 *X0 = (const float4 *)s->u.cell.xs[0];
    const float4 *X1 = (const float4 *)s->u.cell.xs[1];
    const float4 *X2 = (const float4 *)s->u.cell.xs[2];
    const float4 *X3 = (const float4 *)s->u.cell.xs[3];
    const int C = Kc >> 7;   // 128-float chunks: 6 (cell0) or 4

    // 128 units = (gate g, jj) ; warp w handles units [16w, 16w+16)
#pragma unroll 2
    for (int i = 0; i < 16; i++) {
        int u = w * 16 + i;
        int g = u & 3, jj = u >> 2;
        int r = g * 256 + j0 + jj;
        const float4 *wr = (const float4 *)(W + (size_t)r * Kc);
        float a0 = 0.f, a1 = 0.f, a2 = 0.f, a3 = 0.f;
        for (int c = 0; c < C; c++) {
            float4 wv = wr[c * 32 + lane];
            a0 += dot4(wv, X0[c * 32 + lane]);
            a1 += dot4(wv, X1[c * 32 + lane]);
            a2 += dot4(wv, X2[c * 32 + lane]);
            a3 += dot4(wv, X3[c * 32 + lane]);
        }
#pragma unroll
        for (int off = 16; off; off >>= 1) {
            a0 += __shfl_xor_sync(0xffffffffu, a0, off);
            a1 += __shfl_xor_sync(0xffffffffu, a1, off);
            a2 += __shfl_xor_sync(0xffffffffu, a2, off);
            a3 += __shfl_xor_sync(0xffffffffu, a3, off);
        }
        if (lane == 0) {
            float bb = bias[r];
            s->u.cell.gsm[(jj * 4 + g) * 4 + 0] = a0 + bb;
            s->u.cell.gsm[(jj * 4 + g) * 4 + 1] = a1 + bb;
            s->u.cell.gsm[(jj * 4 + g) * 4 + 2] = a2 + bb;
            s->u.cell.gsm[(jj * 4 + g) * 4 + 3] = a3 + bb;
        }
    }
    __syncthreads();
    if (tid < 128) {
        int jj = tid >> 2, bi = tid & 3;
        int b = b0 + bi, j = j0 + jj;
        float gi = s->u.cell.gsm[(jj * 4 + 0) * 4 + bi];
        float gf = s->u.cell.gsm[(jj * 4 + 1) * 4 + bi];
        float gg = s->u.cell.gsm[(jj * 4 + 2) * 4 + bi];
        float go = s->u.cell.gsm[(jj * 4 + 3) * 4 + bi];
        float co = g_c[L][b][j];
        float cn = sigm(gf) * co + sigm(gi) * tanhx(gg);
        g_c[L][b][j] = cn;
        g_h[cur][L][b][j] = sigm(go) * tanhx(cn);
    }
}

// ---------------- MLP head for one batch (4-way interleaved fc1) ----------------
__device__ void mlp_b(int b, int hp, int ol,
                      const float *__restrict__ fc1w, const float *__restrict__ fc1b,
                      const float *__restrict__ fc2w, const float *__restrict__ fc2b,
                      float *__restrict__ out, SM *s)
{
    const int tid = threadIdx.x, w = tid >> 5, lane = tid & 31;
    __syncthreads();
    float rd = 1.0f / g_denom[b];
    s->u.mlp.zs[tid]       = g_h[hp][2][b][tid];
    s->u.mlp.zs[256 + tid] = g_ctxU[b][tid] * rd;
    __syncthreads();
    const float4 *z4 = (const float4 *)s->u.mlp.zs;
    float4 zr0 = z4[0 * 32 + lane], zr1 = z4[1 * 32 + lane];
    float4 zr2 = z4[2 * 32 + lane], zr3 = z4[3 * 32 + lane];
#pragma unroll
    for (int half = 0; half < 2; half++) {
        int base = w * 32 + half * 256;
        for (int i = 0; i < 8; i++) {
            int r0 = base + i, r1 = base + i + 8, r2 = base + i + 16, r3 = base + i + 24;
            const float4 *w0 = (const float4 *)(fc1w + (size_t)r0 * 512);
            const float4 *w1 = (const float4 *)(fc1w + (size_t)r1 * 512);
            const float4 *w2 = (const float4 *)(fc1w + (size_t)r2 * 512);
            const float4 *w3 = (const float4 *)(fc1w + (size_t)r3 * 512);
            float a0 = dot4(w0[0 * 32 + lane], zr0) + dot4(w0[1 * 32 + lane], zr1)
                     + dot4(w0[2 * 32 + lane], zr2) + dot4(w0[3 * 32 + lane], zr3);
            float a1 = dot4(w1[0 * 32 + lane], zr0) + dot4(w1[1 * 32 + lane], zr1)
                     + dot4(w1[2 * 32 + lane], zr2) + dot4(w1[3 * 32 + lane], zr3);
            float a2 = dot4(w2[0 * 32 + lane], zr0) + dot4(w2[1 * 32 + lane], zr1)
                     + dot4(w2[2 * 32 + lane], zr2) + dot4(w2[3 * 32 + lane], zr3);
            float a3 = dot4(w3[0 * 32 + lane], zr0) + dot4(w3[1 * 32 + lane], zr1)
                     + dot4(w3[2 * 32 + lane], zr2) + dot4(w3[3 * 32 + lane], zr3);
#pragma unroll
            for (int off = 16; off; off >>= 1) {
                a0 += __shfl_xor_sync(0xffffffffu, a0, off);
                a1 += __shfl_xor_sync(0xffffffffu, a1, off);
                a2 += __shfl_xor_sync(0xffffffffu, a2, off);
                a3 += __shfl_xor_sync(0xffffffffu, a3, off);
            }
            if (lane == 0) {
                s->u.mlp.hs[r0] = fmaxf(a0 + fc1b[r0], 0.0f);
                s->u.mlp.hs[r1] = fmaxf(a1 + fc1b[r1], 0.0f);
                s->u.mlp.hs[r2] = fmaxf(a2 + fc1b[r2], 0.0f);
                s->u.mlp.hs[r3] = fmaxf(a3 + fc1b[r3], 0.0f);
            }
        }
    }
    __syncthreads();
    const float4 *h4 = (const float4 *)s->u.mlp.hs;
    for (int r = w; r < Vn; r += 8) {
        const float4 *wr = (const float4 *)(fc2w + (size_t)r * 512);
        float a = dot4(wr[0 * 32 + lane], h4[0 * 32 + lane])
                + dot4(wr[1 * 32 + lane], h4[1 * 32 + lane])
                + dot4(wr[2 * 32 + lane], h4[2 * 32 + lane])
                + dot4(wr[3 * 32 + lane], h4[3 * 32 + lane]);
#pragma unroll
        for (int off = 16; off; off >>= 1) a += __shfl_xor_sync(0xffffffffu, a, off);
        if (lane == 0) out[((size_t)b * Ln + ol) * Vn + r] = a + fc2b[r];
    }
}

// ---------------- energy: e[b,t] = key[b,t,:].q[b,:] for t < len[b] (4x unrolled) ----
__device__ void energy_phase(int cur, const float *__restrict__ key,
                             const int *__restrict__ lens, SM *s)
{
    const int blk = blockIdx.x, tid = threadIdx.x;
    const int w = tid >> 5, lane = tid & 31;
    for (int it = blk; it < Bn * 16; it += GRID) {
        int b = it >> 4;
        int t0 = (it & 15) << 7;
        int len = lens[b];
        if (t0 >= len) continue;
        int t1 = min(t0 + 128, len);
        __syncthreads();
        s->u.en.qs[tid] = g_h[cur][2][b][tid];
        __syncthreads();
        const float4 *q4 = (const float4 *)s->u.en.qs;
        float4 q0 = q4[lane], q1 = q4[lane + 32];
        float wmax = -FLT_MAX;
        int tw0 = t0 + w * 16;
        int tw1 = min(tw0 + 16, t1);
        for (int t = tw0; t < tw1; t += 4) {
            int n = min(4, tw1 - t);
            float4 k0[4], k1[4];
            float sv[4];
#pragma unroll
            for (int i = 0; i < 4; i++) {
                if (i < n) {
                    const float4 *kr = (const float4 *)(key + ((size_t)b * Tn + (t + i)) * Hn);
                    k0[i] = kr[lane]; k1[i] = kr[lane + 32];
                }
            }
#pragma unroll
            for (int i = 0; i < 4; i++)
                sv[i] = (i < n) ? (dot4(k0[i], q0) + dot4(k1[i], q1)) : 0.0f;
#pragma unroll
            for (int off = 16; off; off >>= 1) {
#pragma unroll
                for (int i = 0; i < 4; i++)
                    sv[i] += __shfl_xor_sync(0xffffffffu, sv[i], off);
            }
#pragma unroll
            for (int i = 0; i < 4; i++) {
                if (i < n) {
                    if (lane == 0) g_e[b][t + i] = sv[i];
                    wmax = fmaxf(wmax, sv[i]);
                }
            }
        }
        if (lane == 0) s->u.en.wm[w] = wmax;
        __syncthreads();
        if (tid == 0) {
            float m = s->u.en.wm[0];
            for (int i = 1; i < 8; i++) m = fmaxf(m, s->u.en.wm[i]);
            if (m > -FLT_MAX) atomicMax(&g_emax[b], ford(m));
        }
    }
}

// ---------------- ctx: ctxU += exp(e - emax) * value ; denom += exp (4x unrolled) ----
__device__ void ctx_phase(const float *__restrict__ value,
                          const int *__restrict__ lens, SM *s)
{
    const int blk = blockIdx.x, tid = threadIdx.x;
    const int w = tid >> 5, lane = tid & 31;
    for (int it = blk; it < Bn * 16; it += GRID) {
        int b = it >> 4;
        int t0 = (it & 15) << 7;
        int len = lens[b];
        if (t0 >= len) continue;
        int t1 = min(t0 + 128, len);
        float em = fdec(g_emax[b]);
        float4 a0 = make_float4(0.f, 0.f, 0.f, 0.f);
        float4 a1 = make_float4(0.f, 0.f, 0.f, 0.f);
        float dp = 0.0f;
        int tw0 = t0 + w * 16;
        int tw1 = min(tw0 + 16, t1);
        for (int t = tw0; t < tw1; t += 4) {
            int n = min(4, tw1 - t);
            float ev[4];
            float4 v0[4], v1[4];
#pragma unroll
            for (int i = 0; i < 4; i++)
                ev[i] = (i < n) ? g_e[b][t + i] : em;
#pragma unroll
            for (int i = 0; i < 4; i++) {
                if (i < n) {
                    const float4 *vr = (const float4 *)(value + ((size_t)b * Tn + (t + i)) * Hn);
                    v0[i] = vr[lane]; v1[i] = vr[lane + 32];
                } else {
                    v0[i] = make_float4(0.f, 0.f, 0.f, 0.f);
                    v1[i] = make_float4(0.f, 0.f, 0.f, 0.f);
                }
            }
            float p[4];
#pragma unroll
            for (int i = 0; i < 4; i++)
                p[i] = (i < n) ? __expf(ev[i] - em) : 0.0f;
#pragma unroll
            for (int i = 0; i < 4; i++) {
                a0.x = fmaf(p[i], v0[i].x, a0.x); a0.y = fmaf(p[i], v0[i].y, a0.y);
                a0.z = fmaf(p[i], v0[i].z, a0.z); a0.w = fmaf(p[i], v0[i].w, a0.w);
                a1.x = fmaf(p[i], v1[i].x, a1.x); a1.y = fmaf(p[i], v1[i].y, a1.y);
                a1.z = fmaf(p[i], v1[i].z, a1.z); a1.w = fmaf(p[i], v1[i].w, a1.w);
                dp += p[i];
            }
        }
        __syncthreads();
        s->u.ctx.cs[w][lane] = a0;
        s->u.ctx.cs[w][lane + 32] = a1;
        if (lane == 0) s->u.ctx.rs[w] = dp;
        __syncthreads();
        if (tid < 64) {
            float4 sum = s->u.ctx.cs[0][tid];
#pragma unroll
            for (int i = 1; i < 8; i++) {
                float4 v = s->u.ctx.cs[i][tid];
                sum.x += v.x; sum.y += v.y; sum.z += v.z; sum.w += v.w;
            }
            atomicAdd(&g_ctxU[b][4 * tid + 0], sum.x);
            atomicAdd(&g_ctxU[b][4 * tid + 1], sum.y);
            atomicAdd(&g_ctxU[b][4 * tid + 2], sum.z);
            atomicAdd(&g_ctxU[b][4 * tid + 3], sum.w);
        } else if (tid == 64) {
            float d = 0.0f;
#pragma unroll
            for (int i = 0; i < 8; i++) d += s->u.ctx.rs[i];
            atomicAdd(&g_denom[b], d);
        }
    }
}

// ---------------- main persistent kernel ----------------
__global__ __launch_bounds__(NT) void decoder_kernel(
    const float *__restrict__ key, const float *__restrict__ value,
    const int *__restrict__ labels, const int *__restrict__ lens,
    const float *__restrict__ emb,
    const float *__restrict__ fc1w, const float *__restrict__ fc1b,
    const float *__restrict__ fc2w, const float *__restrict__ fc2b,
    float *__restrict__ out)
{
    __shared__ SM s;
    const int blk = blockIdx.x, tid = threadIdx.x;
    unsigned expect = 0;

    for (int l = 0; l < Ln; l++) {
        const int cur = l & 1, prv = cur ^ 1;
        // ---- slot 1: cell0  |  MLP(l-1) part A (b in [0,22)) ----
        if (blk < CELLB) {
            cell_phase(0, l, cur, prv, emb, labels, &s);
        } else if (l > 0) {
            int m = blk - CELLB;
            for (int b = m; b < 22; b += NMLPB)
                mlp_b(b, prv, l - 1, fc1w, fc1b, fc2w, fc2b, out, &s);
        }
        gsync(expect);
        // ---- slot 2: cell1 + emax reset  |  MLP part B (b in [22,44)) ----
        if (blk < CELLB) {
            cell_phase(1, l, cur, prv, emb, labels, &s);
            if (blk == 0 && tid < Bn) g_emax[tid] = 0u;
        } else if (l > 0) {
            int m = blk - CELLB;
            for (int b = 22 + m; b < 44; b += NMLPB)
                mlp_b(b, prv, l - 1, fc1w, fc1b, fc2w, fc2b, out, &s);
        }
        gsync(expect);
        // ---- slot 3: cell2  |  MLP part C (b in [44,64)) ----
        if (blk < CELLB) {
            cell_phase(2, l, cur, prv, emb, labels, &s);
        } else if (l > 0) {
            int m = blk - CELLB;
            for (int b = 44 + m; b < 64; b += NMLPB)
                mlp_b(b, prv, l - 1, fc1w, fc1b, fc2w, fc2b, out, &s);
        }
        gsync(expect);
        // ---- slot 4: zero ctxU/denom + energy (+ per-b max) ----
        for (int i = blk * NT + tid; i < Bn * Hn; i += GRID * NT)
            ((float *)g_ctxU)[i] = 0.0f;
        if (blk == 0 && tid < Bn) g_denom[tid] = 0.0f;
        energy_phase(cur, key, lens, &s);
        gsync(expect);
        // ---- slot 5: ctx accumulation ----
        ctx_phase(value, lens, &s);
        gsync(expect);
    }
    // final MLP for l = Ln-1 (parity of 199 = 1)
    for (int b = blk; b < Bn; b += GRID)
        mlp_b(b, 1, Ln - 1, fc1w, fc1b, fc2w, fc2b, out, &s);
}

// ---------------- launch ----------------
extern "C" void kernel_launch(void *const *d_in, const int *in_sizes, int n_in,
                              void *d_out, int out_size)
{
    const float *key    = (const float *)d_in[0];
    const float *value  = (const float *)d_in[1];
    const int   *labels = (const int *)d_in[2];
    const int   *lens   = (const int *)d_in[3];
    const float *emb    = (const float *)d_in[4];
    const float *w_ih0  = (const float *)d_in[5];
    const float *w_hh0  = (const float *)d_in[6];
    const float *b_ih0  = (const float *)d_in[7];
    const float *b_hh0  = (const float *)d_in[8];
    const float *w_ih_r = (const float *)d_in[9];
    const float *w_hh_r = (const float *)d_in[10];
    const float *b_ih_r = (const float *)d_in[11];
    const float *b_hh_r = (const float *)d_in[12];
    const float *fc1w   = (const float *)d_in[13];
    const float *fc1b   = (const float *)d_in[14];
    const float *fc2w   = (const float *)d_in[15];
    const float *fc2b   = (const float *)d_in[16];
    float *out = (float *)d_out;

    prep_kernel<<<592, 256>>>(w_ih0, w_hh0, b_ih0, b_hh0,
                              w_ih_r, w_hh_r, b_ih_r, b_hh_r);
    decoder_kernel<<<GRID, NT>>>(key, value, labels, lens, emb,
                                 fc1w, fc1b, fc2w, fc2b, out);
}

// round 14
// speedup vs baseline: 1.6475x; 1.1767x over previous
#include <cuda_runtime.h>
#include <math.h>
#include <float.h>

#define GRID  148
#define NT    256
#define CELLB 128      // blocks [0,CELLB) do LSTM cells; [CELLB,GRID) do MLP
#define NMLPB (GRID - CELLB)
#define Bn 64
#define Tn 2048
#define Ln 200
#define Hn 256
#define Vn 33

// ---------------- persistent device state ----------------
__device__ float gW0[1024 * 768];          // cell0 rows: [w_ih0_row(512) | w_hh0_row(256)]
__device__ float gW12[2 * 1024 * 512];     // cells 1,2 rows: [w_ih(256) | w_hh(256)]
__device__ float gBias[3 * 1024];          // b_ih + b_hh per layer
__device__ float g_h[2][3][Bn][Hn];        // double-buffered hidden states
__device__ float g_c[3][Bn][Hn];           // cell states (elementwise in-place safe)
__device__ float g_ctxU[2][Bn][Hn];        // UNnormalized context, double-buffered
__device__ float g_denom[2][Bn];           // softmax denominator, double-buffered
__device__ unsigned g_bar;                 // grid barrier counter

struct __align__(16) SM {
    union {
        struct { float xs[4][768]; float gsm[512]; } cell;   // 14.3 KB
        struct { float4 cs[8][64]; float rs[8]; } ctx;       // 8.2 KB
        struct { float zs[2][512]; float hs[2][512]; } mlp;  // 8 KB
    } u;
};

// ---------------- helpers ----------------
__device__ __forceinline__ float sigm(float x) { return 1.0f / (1.0f + __expf(-x)); }
__device__ __forceinline__ float tanhx(float x) {
    float e = __expf(-2.0f * fabsf(x));
    float r = (1.0f - e) / (1.0f + e);
    return x < 0.0f ? -r : r;
}
__device__ __forceinline__ float dot4(float4 a, float4 b) {
    return fmaf(a.x, b.x, fmaf(a.y, b.y, fmaf(a.z, b.z, a.w * b.w)));
}

// grid-wide barrier: monotonic counter (reset by prep each launch)
__device__ __forceinline__ void gsync(unsigned &expect) {
    __syncthreads();
    if (threadIdx.x == 0) {
        expect += GRID;
        __threadfence();
        atomicAdd(&g_bar, 1u);
        while (*((volatile unsigned *)&g_bar) < expect) { }
        __threadfence();
    }
    __syncthreads();
}

// ---------------- prep: concat weights, zero state, reset barrier ----------------
__global__ void prep_kernel(const float *__restrict__ w_ih0, const float *__restrict__ w_hh0,
                            const float *__restrict__ b_ih0, const float *__restrict__ b_hh0,
                            const float *__restrict__ w_ih_r, const float *__restrict__ w_hh_r,
                            const float *__restrict__ b_ih_r, const float *__restrict__ b_hh_r)
{
    const int ns = gridDim.x * blockDim.x;
    const int t0 = blockIdx.x * blockDim.x + threadIdx.x;
    for (int i = t0; i < 1024 * 768; i += ns) {
        int r = i / 768, k = i - r * 768;
        gW0[i] = (k < 512) ? w_ih0[r * 512 + k] : w_hh0[r * 256 + (k - 512)];
    }
    for (int i = t0; i < 2 * 1024 * 512; i += ns) {
        int li = i >> 19;
        int rem = i & ((1 << 19) - 1);
        int r = rem >> 9, k = rem & 511;
        gW12[i] = (k < 256) ? w_ih_r[((size_t)li * 1024 + r) * 256 + k]
                            : w_hh_r[((size_t)li * 1024 + r) * 256 + (k - 256)];
    }
    for (int i = t0; i < 3 * 1024; i += ns) {
        int li = i >> 10, r = i & 1023;
        gBias[i] = (li == 0) ? (b_ih0[r] + b_hh0[r])
                             : (b_ih_r[(li - 1) * 1024 + r] + b_hh_r[(li - 1) * 1024 + r]);
    }
    for (int i = t0; i < 2 * 3 * Bn * Hn; i += ns) ((float *)g_h)[i] = 0.0f;
    for (int i = t0; i < 3 * Bn * Hn; i += ns) ((float *)g_c)[i] = 0.0f;
    for (int i = t0; i < 2 * Bn * Hn; i += ns) ((float *)g_ctxU)[i] = 0.0f;
    for (int i = t0; i < 2 * Bn; i += ns) ((float *)g_denom)[i] = 1.0f;
    if (t0 == 0) g_bar = 0u;
}

// ---------------- LSTM cell phase (blocks 0..127): tile 4b x 32j ----------------
template<int KC>
__device__ void cell_phase(int L, int l, int cur, int prv,
                           const float *__restrict__ W,
                           const float *__restrict__ emb, const int *__restrict__ labels, SM *s)
{
    const int blk = blockIdx.x, tid = threadIdx.x;
    const int w = tid >> 5, lane = tid & 31;
    const int b0 = (blk >> 3) * 4;
    const int j0 = (blk & 7) * 32;
    const float *bias = gBias + L * 1024;

    // stage xcat for 4 batches into smem
    if (L == 0) {
        for (int i = tid; i < 4 * 256; i += NT) {
            int bi = i >> 8, k = i & 255, b = b0 + bi;
            int lab = labels[l * Bn + b];
            float rd = 1.0f / g_denom[prv][b];
            s->u.cell.xs[bi][k]       = emb[(size_t)lab * 256 + k];
            s->u.cell.xs[bi][256 + k] = g_ctxU[prv][b][k] * rd;
            s->u.cell.xs[bi][512 + k] = g_h[prv][0][b][k];
        }
    } else {
        for (int i = tid; i < 4 * 256; i += NT) {
            int bi = i >> 8, k = i & 255, b = b0 + bi;
            s->u.cell.xs[bi][k]       = g_h[cur][L - 1][b][k];
            s->u.cell.xs[bi][256 + k] = g_h[prv][L][b][k];
        }
    }
    __syncthreads();

    const float4 *X0 = (const float4 *)s->u.cell.xs[0];
    const float4 *X1 = (const float4 *)s->u.cell.xs[1];
    const float4 *X2 = (const float4 *)s->u.cell.xs[2];
    const float4 *X3 = (const float4 *)s->u.cell.xs[3];
    constexpr int C = KC >> 7;   // 128-float chunks: 6 (cell0) or 4

    // 128 units = (gate g, jj) ; warp w handles units [16w, 16w+16)
#pragma unroll 2
    for (int i = 0; i < 16; i++) {
        int u = w * 16 + i;
        int g = u & 3, jj = u >> 2;
        int r = g * 256 + j0 + jj;
        const float4 *wr = (const float4 *)(W + (size_t)r * KC);
        float a0 = 0.f, a1 = 0.f, a2 = 0.f, a3 = 0.f;
#pragma unroll
        for (int c = 0; c < C; c++) {
            float4 wv = wr[c * 32 + lane];
            a0 += dot4(wv, X0[c * 32 + lane]);
            a1 += dot4(wv, X1[c * 32 + lane]);
            a2 += dot4(wv, X2[c * 32 + lane]);
            a3 += dot4(wv, X3[c * 32 + lane]);
        }
#pragma unroll
        for (int off = 16; off; off >>= 1) {
            a0 += __shfl_xor_sync(0xffffffffu, a0, off);
            a1 += __shfl_xor_sync(0xffffffffu, a1, off);
            a2 += __shfl_xor_sync(0xffffffffu, a2, off);
            a3 += __shfl_xor_sync(0xffffffffu, a3, off);
        }
        if (lane == 0) {
            float bb = bias[r];
            s->u.cell.gsm[(jj * 4 + g) * 4 + 0] = a0 + bb;
            s->u.cell.gsm[(jj * 4 + g) * 4 + 1] = a1 + bb;
            s->u.cell.gsm[(jj * 4 + g) * 4 + 2] = a2 + bb;
            s->u.cell.gsm[(jj * 4 + g) * 4 + 3] = a3 + bb;
        }
    }
    __syncthreads();
    if (tid < 128) {
        int jj = tid >> 2, bi = tid & 3;
        int b = b0 + bi, j = j0 + jj;
        float gi = s->u.cell.gsm[(jj * 4 + 0) * 4 + bi];
        float gf = s->u.cell.gsm[(jj * 4 + 1) * 4 + bi];
        float gg = s->u.cell.gsm[(jj * 4 + 2) * 4 + bi];
        float go = s->u.cell.gsm[(jj * 4 + 3) * 4 + bi];
        float co = g_c[L][b][j];
        float cn = sigm(gf) * co + sigm(gi) * tanhx(gg);
        g_c[L][b][j] = cn;
        g_h[cur][L][b][j] = sigm(go) * tanhx(cn);
    }
}

// ---------------- MLP head for a group of 2 batches ----------------
__device__ void mlp_g(int g, int hb, int ol,
                      const float *__restrict__ fc1w, const float *__restrict__ fc1b,
                      const float *__restrict__ fc2w, const float *__restrict__ fc2b,
                      float *__restrict__ out, SM *s)
{
    const int tid = threadIdx.x, w = tid >> 5, lane = tid & 31;
    const int b0 = g * 2;
    __syncthreads();
    for (int i = tid; i < 2 * 512; i += NT) {
        int bi = i >> 9, k = i & 511, b = b0 + bi;
        s->u.mlp.zs[bi][k] = (k < 256) ? g_h[hb][2][b][k]
                                       : g_ctxU[hb][b][k - 256] * (1.0f / g_denom[hb][b]);
    }
    __syncthreads();
    const float4 *z40 = (const float4 *)s->u.mlp.zs[0];
    const float4 *z41 = (const float4 *)s->u.mlp.zs[1];
    float4 z0[4], z1[4];
#pragma unroll
    for (int c = 0; c < 4; c++) { z0[c] = z40[c * 32 + lane]; z1[c] = z41[c * 32 + lane]; }
    // fc1: warp w handles rows [w*64, w*64+64), 2 rows at a time
    for (int r = w * 64; r < w * 64 + 64; r += 2) {
        const float4 *wr0 = (const float4 *)(fc1w + (size_t)r * 512);
        const float4 *wr1 = (const float4 *)(fc1w + (size_t)(r + 1) * 512);
        float a00 = 0.f, a01 = 0.f, a10 = 0.f, a11 = 0.f;
#pragma unroll
        for (int c = 0; c < 4; c++) {
            float4 w0 = wr0[c * 32 + lane], w1 = wr1[c * 32 + lane];
            a00 += dot4(w0, z0[c]); a01 += dot4(w0, z1[c]);
            a10 += dot4(w1, z0[c]); a11 += dot4(w1, z1[c]);
        }
#pragma unroll
        for (int off = 16; off; off >>= 1) {
            a00 += __shfl_xor_sync(0xffffffffu, a00, off);
            a01 += __shfl_xor_sync(0xffffffffu, a01, off);
            a10 += __shfl_xor_sync(0xffffffffu, a10, off);
            a11 += __shfl_xor_sync(0xffffffffu, a11, off);
        }
        if (lane == 0) {
            float bb0 = fc1b[r], bb1 = fc1b[r + 1];
            s->u.mlp.hs[0][r]     = fmaxf(a00 + bb0, 0.0f);
            s->u.mlp.hs[1][r]     = fmaxf(a01 + bb0, 0.0f);
            s->u.mlp.hs[0][r + 1] = fmaxf(a10 + bb1, 0.0f);
            s->u.mlp.hs[1][r + 1] = fmaxf(a11 + bb1, 0.0f);
        }
    }
    __syncthreads();
    const float4 *h40 = (const float4 *)s->u.mlp.hs[0];
    const float4 *h41 = (const float4 *)s->u.mlp.hs[1];
    float4 h0[4], h1[4];
#pragma unroll
    for (int c = 0; c < 4; c++) { h0[c] = h40[c * 32 + lane]; h1[c] = h41[c * 32 + lane]; }
    for (int r = w; r < Vn; r += 8) {
        const float4 *wr = (const float4 *)(fc2w + (size_t)r * 512);
        float a0 = 0.f, a1 = 0.f;
#pragma unroll
        for (int c = 0; c < 4; c++) {
            float4 wv = wr[c * 32 + lane];
            a0 += dot4(wv, h0[c]); a1 += dot4(wv, h1[c]);
        }
#pragma unroll
        for (int off = 16; off; off >>= 1) {
            a0 += __shfl_xor_sync(0xffffffffu, a0, off);
            a1 += __shfl_xor_sync(0xffffffffu, a1, off);
        }
        if (lane == 0) {
            float bb = fc2b[r];
            out[((size_t)b0 * Ln + ol) * Vn + r]       = a0 + bb;
            out[((size_t)(b0 + 1) * Ln + ol) * Vn + r] = a1 + bb;
        }
    }
}

// ------- fused attention: p=exp(e); ctxU[cur] += p*value; denom[cur] += p -------
__device__ void attn_phase(int cur, const float *__restrict__ key,
                           const float *__restrict__ value,
                           const int *__restrict__ lens, SM *s)
{
    const int blk = blockIdx.x, tid = threadIdx.x;
    const int w = tid >> 5, lane = tid & 31;
    for (int it = blk; it < Bn * 16; it += GRID) {
        int b = it >> 4;
        int t0 = (it & 15) << 7;
        int len = lens[b];
        if (t0 >= len) continue;
        int t1 = min(t0 + 128, len);
        const float4 *q4 = (const float4 *)g_h[cur][2][b];
        float4 q0 = q4[lane], q1 = q4[lane + 32];
        float4 a0 = make_float4(0.f, 0.f, 0.f, 0.f);
        float4 a1 = make_float4(0.f, 0.f, 0.f, 0.f);
        float dp = 0.0f;
        int tw0 = t0 + w * 16;
        int tw1 = min(tw0 + 16, t1);
        for (int t = tw0; t < tw1; t += 4) {
            int n = min(4, tw1 - t);
            float4 k0[4], k1[4], v0[4], v1[4];
#pragma unroll
            for (int i = 0; i < 4; i++) {
                if (i < n) {
                    const float4 *kr = (const float4 *)(key + ((size_t)b * Tn + (t + i)) * Hn);
                    const float4 *vr = (const float4 *)(value + ((size_t)b * Tn + (t + i)) * Hn);
                    k0[i] = kr[lane]; k1[i] = kr[lane + 32];
                    v0[i] = vr[lane]; v1[i] = vr[lane + 32];
                }
            }
            float sv[4];
#pragma unroll
            for (int i = 0; i < 4; i++)
                sv[i] = (i < n) ? (dot4(k0[i], q0) + dot4(k1[i], q1)) : -1e30f;
#pragma unroll
            for (int off = 16; off; off >>= 1) {
#pragma unroll
                for (int i = 0; i < 4; i++)
                    sv[i] += __shfl_xor_sync(0xffffffffu, sv[i], off);
            }
            float p[4];
#pragma unroll
            for (int i = 0; i < 4; i++)
                p[i] = __expf(fminf(sv[i], 75.0f));   // sv=-4e30 -> 0
#pragma unroll
            for (int i = 0; i < 4; i++) {
                if (i < n) {
                    a0.x = fmaf(p[i], v0[i].x, a0.x); a0.y = fmaf(p[i], v0[i].y, a0.y);
                    a0.z = fmaf(p[i], v0[i].z, a0.z); a0.w = fmaf(p[i], v0[i].w, a0.w);
                    a1.x = fmaf(p[i], v1[i].x, a1.x); a1.y = fmaf(p[i], v1[i].y, a1.y);
                    a1.z = fmaf(p[i], v1[i].z, a1.z); a1.w = fmaf(p[i], v1[i].w, a1.w);
                    dp += p[i];
                }
            }
        }
        __syncthreads();
        s->u.ctx.cs[w][lane] = a0;
        s->u.ctx.cs[w][lane + 32] = a1;
        if (lane == 0) s->u.ctx.rs[w] = dp;   // dp already warp-total (replicated)
        __syncthreads();
        if (tid < 64) {
            float4 sum = s->u.ctx.cs[0][tid];
#pragma unroll
            for (int i = 1; i < 8; i++) {
                float4 v = s->u.ctx.cs[i][tid];
                sum.x += v.x; sum.y += v.y; sum.z += v.z; sum.w += v.w;
            }
            atomicAdd(&g_ctxU[cur][b][4 * tid + 0], sum.x);
            atomicAdd(&g_ctxU[cur][b][4 * tid + 1], sum.y);
            atomicAdd(&g_ctxU[cur][b][4 * tid + 2], sum.z);
            atomicAdd(&g_ctxU[cur][b][4 * tid + 3], sum.w);
        } else if (tid == 64) {
            float d = 0.0f;
#pragma unroll
            for (int i = 0; i < 8; i++) d += s->u.ctx.rs[i];
            atomicAdd(&g_denom[cur][b], d);
        }
    }
}

// ---------------- main persistent kernel ----------------
__global__ __launch_bounds__(NT) void decoder_kernel(
    const float *__restrict__ key, const float *__restrict__ value,
    const int *__restrict__ labels, const int *__restrict__ lens,
    const float *__restrict__ emb,
    const float *__restrict__ fc1w, const float *__restrict__ fc1b,
    const float *__restrict__ fc2w, const float *__restrict__ fc2b,
    float *__restrict__ out)
{
    __shared__ SM s;
    const int blk = blockIdx.x, tid = threadIdx.x;
    unsigned expect = 0;

    for (int l = 0; l < Ln; l++) {
        const int cur = l & 1, prv = cur ^ 1;
        // ---- slot 1: zero ctxU[cur]/denom[cur]; cell0 | MLP groups [0,11) ----
        {
            int i = blk * NT + tid;
            if (i < Bn * Hn) ((float *)g_ctxU[cur])[i] = 0.0f;
            if (blk == GRID - 1 && tid < Bn) g_denom[cur][tid] = 0.0f;
        }
        if (blk < CELLB) {
            cell_phase<768>(0, l, cur, prv, gW0, emb, labels, &s);
        } else if (l > 0) {
            int m = blk - CELLB;
            if (m < 11) mlp_g(m, prv, l - 1, fc1w, fc1b, fc2w, fc2b, out, &s);
        }
        gsync(expect);
        // ---- slot 2: cell1 | MLP groups [11,22) ----
        if (blk < CELLB) {
            cell_phase<512>(1, l, cur, prv, gW12, emb, labels, &s);
        } else if (l > 0) {
            int m = blk - CELLB;
            if (m < 11) mlp_g(11 + m, prv, l - 1, fc1w, fc1b, fc2w, fc2b, out, &s);
        }
        gsync(expect);
        // ---- slot 3: cell2 | MLP groups [22,32) ----
        if (blk < CELLB) {
            cell_phase<512>(2, l, cur, prv, gW12 + (size_t)1024 * 512, emb, labels, &s);
        } else if (l > 0) {
            int m = blk - CELLB;
            if (m < 10) mlp_g(22 + m, prv, l - 1, fc1w, fc1b, fc2w, fc2b, out, &s);
        }
        gsync(expect);
        // ---- slot 4: fused attention ----
        attn_phase(cur, key, value, lens, &s);
        gsync(expect);
    }
    // final MLP for l = Ln-1 (buffer parity of 199 = 1)
    for (int g = blk; g < 32; g += GRID)
        mlp_g(g, 1, Ln - 1, fc1w, fc1b, fc2w, fc2b, out, &s);
}

// ---------------- launch ----------------
extern "C" void kernel_launch(void *const *d_in, const int *in_sizes, int n_in,
                              void *d_out, int out_size)
{
    const float *key    = (const float *)d_in[0];
    const float *value  = (const float *)d_in[1];
    const int   *labels = (const int *)d_in[2];
    const int   *lens   = (const int *)d_in[3];
    const float *emb    = (const float *)d_in[4];
    const float *w_ih0  = (const float *)d_in[5];
    const float *w_hh0  = (const float *)d_in[6];
    const float *b_ih0  = (const float *)d_in[7];
    const float *b_hh0  = (const float *)d_in[8];
    const float *w_ih_r = (const float *)d_in[9];
    const float *w_hh_r = (const float *)d_in[10];
    const float *b_ih_r = (const float *)d_in[11];
    const float *b_hh_r = (const float *)d_in[12];
    const float *fc1w   = (const float *)d_in[13];
    const float *fc1b   = (const float *)d_in[14];
    const float *fc2w   = (const float *)d_in[15];
    const float *fc2b   = (const float *)d_in[16];
    float *out = (float *)d_out;

    prep_kernel<<<592, 256>>>(w_ih0, w_hh0, b_ih0, b_hh0,
                              w_ih_r, w_hh_r, b_ih_r, b_hh_r);
    decoder_kernel<<<GRID, NT>>>(key, value, labels, lens, emb,
                                 fc1w, fc1b, fc2w, fc2b, out);
}